// round 5
// baseline (speedup 1.0000x reference)
#include <cuda_runtime.h>
#include <cuda_bf16.h>
#include <cuda_fp16.h>
#include <cstdint>
#include <math.h>

// Problem constants (fixed by the reference)
#define NNODES 100000
#define NEDGES 1600000
#define DFEAT  128
#define HEADS  4
#define DHEAD  32
#define NEG_SLOPE 0.2f

// ---------------- scratch (static device globals; no allocations) ------------
__device__ int    g_deg[NNODES];
__device__ int    g_cursor[NNODES];
__device__ int    g_off[NNODES];
__device__ int    g_total;
__device__ int    g_csr[NEDGES];
__device__ float  g_w[(size_t)NEDGES * HEADS];      // spill path for deg>32 nodes
__device__ float  g_bufA[(size_t)NNODES * DFEAT];   // GEMM output h (fp32)
__device__ float  g_bufB[(size_t)NNODES * DFEAT];   // layer-1 aggregated + relu
__device__ __half g_h16[(size_t)NNODES * DFEAT];    // fp16 copy of h for gather
__device__ float  g_es[NNODES * HEADS];
__device__ float  g_ed[NNODES * HEADS];

// ---------------- CSR build --------------------------------------------------
__global__ void count_kernel(const int* __restrict__ dst, int e) {
    int i = blockIdx.x * blockDim.x + threadIdx.x;
    if (i < e) atomicAdd(&g_deg[dst[i]], 1);
}

// Unordered CSR offsets: each node grabs a contiguous range via one
// warp-aggregated atomic (warp inclusive scan + single atomicAdd per warp).
__global__ void offsets_kernel(int n) {
    int i = blockIdx.x * blockDim.x + threadIdx.x;
    int lane = threadIdx.x & 31;
    int d = (i < n) ? g_deg[i] : 0;
    int inc = d;
#pragma unroll
    for (int o = 1; o < 32; o <<= 1) {
        int t = __shfl_up_sync(0xffffffffu, inc, o);
        if (lane >= o) inc += t;
    }
    int warpTot = __shfl_sync(0xffffffffu, inc, 31);
    int base = 0;
    if (lane == 31) base = atomicAdd(&g_total, warpTot);
    base = __shfl_sync(0xffffffffu, base, 31);
    int off = base + inc - d;
    if (i < n) { g_off[i] = off; g_cursor[i] = off; }
}

__global__ void scatter_kernel(const int* __restrict__ src,
                               const int* __restrict__ dst, int e) {
    int i = blockIdx.x * blockDim.x + threadIdx.x;
    if (i < e) {
        int d = dst[i];
        int slot = atomicAdd(&g_cursor[d], 1);
        g_csr[slot] = src[i];
    }
}

// ---------------- GEMM: out[M,128] = X[M,128] @ W[128,128] -------------------
// tf32 tensor-core path with 3xTF32 error compensation.
// Epilogue also writes an fp16 copy of the output for the gather phase.
#define XS_STRIDE 132
#define WS_STRIDE 136
#define GEMM_SMEM ((128 * XS_STRIDE + 128 * WS_STRIDE) * 4)

__device__ __forceinline__ void split_tf32(float x, uint32_t& hi, uint32_t& lo) {
    asm("cvt.rna.tf32.f32 %0, %1;" : "=r"(hi) : "f"(x));
    float r = x - __uint_as_float(hi);
    asm("cvt.rna.tf32.f32 %0, %1;" : "=r"(lo) : "f"(r));
}

__device__ __forceinline__ void mma_tf32(float* d, const uint32_t* a, const uint32_t* b) {
    asm volatile(
        "mma.sync.aligned.m16n8k8.row.col.f32.tf32.tf32.f32 "
        "{%0,%1,%2,%3}, {%4,%5,%6,%7}, {%8,%9}, {%0,%1,%2,%3};\n"
        : "+f"(d[0]), "+f"(d[1]), "+f"(d[2]), "+f"(d[3])
        : "r"(a[0]), "r"(a[1]), "r"(a[2]), "r"(a[3]),
          "r"(b[0]), "r"(b[1]));
}

__global__ __launch_bounds__(256, 1)
void gemm_tf32_kernel(const float* __restrict__ X, const float* __restrict__ W,
                      float* __restrict__ out, int M) {
    extern __shared__ float sm[];
    float* Xs = sm;                        // [128][XS_STRIDE]
    float* Ws = sm + 128 * XS_STRIDE;      // [128][WS_STRIDE]
    int tid = threadIdx.x;
    int rowBase = blockIdx.x * 128;

#pragma unroll 4
    for (int i = tid; i < 128 * 32; i += 256) {
        int r = i >> 5, c4 = (i & 31) << 2;
        int gr = rowBase + r;
        float4 v = make_float4(0.f, 0.f, 0.f, 0.f);
        if (gr < M) v = *(const float4*)&X[(size_t)gr * 128 + c4];
        *(float4*)&Xs[r * XS_STRIDE + c4] = v;
    }
#pragma unroll 4
    for (int i = tid; i < 128 * 32; i += 256) {
        int r = i >> 5, c4 = (i & 31) << 2;
        *(float4*)&Ws[r * WS_STRIDE + c4] = *(const float4*)&W[(size_t)r * 128 + c4];
    }
    __syncthreads();

    int lane = tid & 31, warp = tid >> 5;
    int g = lane >> 2, t = lane & 3;
    int wm = (warp & 3) * 32;
    int wn = (warp >> 2) * 64;

    float acc[2][8][4];
#pragma unroll
    for (int mb = 0; mb < 2; mb++)
#pragma unroll
        for (int nb = 0; nb < 8; nb++)
#pragma unroll
            for (int i = 0; i < 4; i++) acc[mb][nb][i] = 0.f;

    for (int kc = 0; kc < 128; kc += 8) {
        uint32_t ahi[2][4], alo[2][4];
#pragma unroll
        for (int mb = 0; mb < 2; mb++) {
            int r0 = wm + mb * 16;
            float x0 = Xs[(r0 + g) * XS_STRIDE + kc + t];
            float x1 = Xs[(r0 + g + 8) * XS_STRIDE + kc + t];
            float x2 = Xs[(r0 + g) * XS_STRIDE + kc + t + 4];
            float x3 = Xs[(r0 + g + 8) * XS_STRIDE + kc + t + 4];
            split_tf32(x0, ahi[mb][0], alo[mb][0]);
            split_tf32(x1, ahi[mb][1], alo[mb][1]);
            split_tf32(x2, ahi[mb][2], alo[mb][2]);
            split_tf32(x3, ahi[mb][3], alo[mb][3]);
        }
        uint32_t bhi[8][2], blo[8][2];
#pragma unroll
        for (int nb = 0; nb < 8; nb++) {
            int n = wn + nb * 8 + g;
            float y0 = Ws[(kc + t) * WS_STRIDE + n];
            float y1 = Ws[(kc + t + 4) * WS_STRIDE + n];
            split_tf32(y0, bhi[nb][0], blo[nb][0]);
            split_tf32(y1, bhi[nb][1], blo[nb][1]);
        }
#pragma unroll
        for (int mb = 0; mb < 2; mb++)
#pragma unroll
            for (int nb = 0; nb < 8; nb++) {
                mma_tf32(acc[mb][nb], ahi[mb], blo[nb]);
                mma_tf32(acc[mb][nb], alo[mb], bhi[nb]);
                mma_tf32(acc[mb][nb], ahi[mb], bhi[nb]);
            }
    }

#pragma unroll
    for (int mb = 0; mb < 2; mb++)
#pragma unroll
        for (int nb = 0; nb < 8; nb++) {
            int row0 = rowBase + wm + mb * 16 + g;
            int col = wn + nb * 8 + 2 * t;
            if (row0 < M) {
                float2 v; v.x = acc[mb][nb][0]; v.y = acc[mb][nb][1];
                *(float2*)&out[(size_t)row0 * 128 + col] = v;
                *(__half2*)&g_h16[(size_t)row0 * 128 + col] = __float22half2_rn(v);
            }
            int row1 = row0 + 8;
            if (row1 < M) {
                float2 v; v.x = acc[mb][nb][2]; v.y = acc[mb][nb][3];
                *(float2*)&out[(size_t)row1 * 128 + col] = v;
                *(__half2*)&g_h16[(size_t)row1 * 128 + col] = __float22half2_rn(v);
            }
        }
}

// ---------------- per-node attention logits e_src/e_dst ----------------------
__device__ __forceinline__ float warp_sum(float v) {
#pragma unroll
    for (int o = 16; o; o >>= 1) v += __shfl_xor_sync(0xffffffffu, v, o);
    return v;
}

__device__ __forceinline__ float warp_max(float v) {
#pragma unroll
    for (int o = 16; o; o >>= 1) v = fmaxf(v, __shfl_xor_sync(0xffffffffu, v, o));
    return v;
}

__global__ void compute_e_kernel(const float* __restrict__ h,
                                 const float* __restrict__ asrc,
                                 const float* __restrict__ adst,
                                 float* __restrict__ es, float* __restrict__ ed,
                                 int n) {
    int w = (blockIdx.x * blockDim.x + threadIdx.x) >> 5;
    int lane = threadIdx.x & 31;
    if (w >= n) return;
    const float* hp = h + (size_t)w * 128;
    float v0 = hp[lane], v1 = hp[32 + lane], v2 = hp[64 + lane], v3 = hp[96 + lane];
    float s0 = warp_sum(v0 * __ldg(&asrc[lane]));
    float s1 = warp_sum(v1 * __ldg(&asrc[32 + lane]));
    float s2 = warp_sum(v2 * __ldg(&asrc[64 + lane]));
    float s3 = warp_sum(v3 * __ldg(&asrc[96 + lane]));
    float d0 = warp_sum(v0 * __ldg(&adst[lane]));
    float d1 = warp_sum(v1 * __ldg(&adst[32 + lane]));
    float d2 = warp_sum(v2 * __ldg(&adst[64 + lane]));
    float d3 = warp_sum(v3 * __ldg(&adst[96 + lane]));
    if (lane == 0) {
        *(float4*)&es[w * 4] = make_float4(s0, s1, s2, s3);
        *(float4*)&ed[w * 4] = make_float4(d0, d1, d2, d3);
    }
}

// ---------------- aggregation: one warp per destination node -----------------
__device__ __forceinline__ float lrelu(float x) {
    return x > 0.f ? x : NEG_SLOPE * x;
}

// Layout: lane owns features [4*lane, 4*lane+4) -> all in head (lane>>3).
// Gather reads the fp16 h table (8B per lane per edge); accumulate fp32.
// mode 0: out = relu(agg + bias); mode 1: out = log_softmax(agg + bias)
__global__ __launch_bounds__(256)
void aggregate_kernel(const float* __restrict__ es,
                      const float* __restrict__ ed, const float* __restrict__ bias,
                      float* __restrict__ out, int n, int mode) {
    __shared__ int   sm_s[8][32];
    __shared__ float sm_a[8][32][4];
    int wi = threadIdx.x >> 5;
    int w = blockIdx.x * 8 + wi;
    int lane = threadIdx.x & 31;
    if (w >= n) return;
    int beg = g_off[w];
    int deg = g_deg[w];
    int end = beg + deg;
    float4 edv = *(const float4*)&ed[w * 4];
    int head = lane >> 3;

    float acc0 = 0.f, acc1 = 0.f, acc2 = 0.f, acc3 = 0.f;

    if (deg <= 32) {
        // ---- fast path: single chunk, everything in registers ----
        int j = beg + lane;
        int s = 0;
        float c0 = -1e30f, c1 = -1e30f, c2 = -1e30f, c3 = -1e30f;
        if (j < end) {
            s = g_csr[j];
            float4 e = *(const float4*)&es[s * 4];
            c0 = lrelu(e.x + edv.x); c1 = lrelu(e.y + edv.y);
            c2 = lrelu(e.z + edv.z); c3 = lrelu(e.w + edv.w);
        }
        float m0 = warp_max(c0), m1 = warp_max(c1);
        float m2 = warp_max(c2), m3 = warp_max(c3);
        float w0 = 0.f, w1 = 0.f, w2 = 0.f, w3 = 0.f;
        if (j < end) {
            w0 = __expf(c0 - m0); w1 = __expf(c1 - m1);
            w2 = __expf(c2 - m2); w3 = __expf(c3 - m3);
        }
        float z0 = warp_sum(w0), z1 = warp_sum(w1);
        float z2 = warp_sum(w2), z3 = warp_sum(w3);
        float i0 = (z0 > 0.f) ? 1.f / z0 : 0.f;
        float i1 = (z1 > 0.f) ? 1.f / z1 : 0.f;
        float i2 = (z2 > 0.f) ? 1.f / z2 : 0.f;
        float i3 = (z3 > 0.f) ? 1.f / z3 : 0.f;

        sm_s[wi][lane] = s;
        *(float4*)&sm_a[wi][lane][0] = make_float4(w0 * i0, w1 * i1, w2 * i2, w3 * i3);
        __syncwarp();
#pragma unroll 4
        for (int k = 0; k < deg; k++) {
            int   sk = sm_s[wi][k];
            float b  = sm_a[wi][k][head];
            uint2 raw = *(const uint2*)&g_h16[(size_t)sk * 128 + lane * 4];
            float2 f0 = __half22float2(*(__half2*)&raw.x);
            float2 f1 = __half22float2(*(__half2*)&raw.y);
            acc0 = fmaf(b, f0.x, acc0); acc1 = fmaf(b, f0.y, acc1);
            acc2 = fmaf(b, f1.x, acc2); acc3 = fmaf(b, f1.y, acc3);
        }
    } else {
        // ---- slow path (deg > 32): spill weights through g_w ----
        float m0 = -1e30f, m1 = -1e30f, m2 = -1e30f, m3 = -1e30f;
        for (int j = beg + lane; j < end; j += 32) {
            int s = g_csr[j];
            float4 e = *(const float4*)&es[s * 4];
            m0 = fmaxf(m0, lrelu(e.x + edv.x)); m1 = fmaxf(m1, lrelu(e.y + edv.y));
            m2 = fmaxf(m2, lrelu(e.z + edv.z)); m3 = fmaxf(m3, lrelu(e.w + edv.w));
        }
        m0 = warp_max(m0); m1 = warp_max(m1); m2 = warp_max(m2); m3 = warp_max(m3);
        float z0 = 0.f, z1 = 0.f, z2 = 0.f, z3 = 0.f;
        for (int j = beg + lane; j < end; j += 32) {
            int s = g_csr[j];
            float4 e = *(const float4*)&es[s * 4];
            float w0 = __expf(lrelu(e.x + edv.x) - m0);
            float w1 = __expf(lrelu(e.y + edv.y) - m1);
            float w2 = __expf(lrelu(e.z + edv.z) - m2);
            float w3 = __expf(lrelu(e.w + edv.w) - m3);
            *(float4*)&g_w[(size_t)j * 4] = make_float4(w0, w1, w2, w3);
            z0 += w0; z1 += w1; z2 += w2; z3 += w3;
        }
        z0 = warp_sum(z0); z1 = warp_sum(z1); z2 = warp_sum(z2); z3 = warp_sum(z3);
        float i0 = (z0 > 0.f) ? 1.f / z0 : 0.f;
        float i1 = (z1 > 0.f) ? 1.f / z1 : 0.f;
        float i2 = (z2 > 0.f) ? 1.f / z2 : 0.f;
        float i3 = (z3 > 0.f) ? 1.f / z3 : 0.f;

        for (int j0 = beg; j0 < end; j0 += 32) {
            int j = j0 + lane;
            __syncwarp();
            if (j < end) {
                sm_s[wi][lane] = g_csr[j];
                float4 wv = *(const float4*)&g_w[(size_t)j * 4];
                *(float4*)&sm_a[wi][lane][0] =
                    make_float4(wv.x * i0, wv.y * i1, wv.z * i2, wv.w * i3);
            }
            __syncwarp();
            int cnt = min(32, end - j0);
#pragma unroll 4
            for (int k = 0; k < cnt; k++) {
                int   sk = sm_s[wi][k];
                float b  = sm_a[wi][k][head];
                uint2 raw = *(const uint2*)&g_h16[(size_t)sk * 128 + lane * 4];
                float2 f0 = __half22float2(*(__half2*)&raw.x);
                float2 f1 = __half22float2(*(__half2*)&raw.y);
                acc0 = fmaf(b, f0.x, acc0); acc1 = fmaf(b, f0.y, acc1);
                acc2 = fmaf(b, f1.x, acc2); acc3 = fmaf(b, f1.y, acc3);
            }
        }
    }

    float4 bv = *(const float4*)&bias[lane * 4];
    acc0 += bv.x; acc1 += bv.y; acc2 += bv.z; acc3 += bv.w;

    float* op = out + (size_t)w * 128 + lane * 4;
    if (mode == 0) {
        float4 v;
        v.x = fmaxf(acc0, 0.f); v.y = fmaxf(acc1, 0.f);
        v.z = fmaxf(acc2, 0.f); v.w = fmaxf(acc3, 0.f);
        *(float4*)op = v;
    } else {
        float mx = fmaxf(fmaxf(acc0, acc1), fmaxf(acc2, acc3));
        mx = warp_max(mx);
        float se = __expf(acc0 - mx) + __expf(acc1 - mx) +
                   __expf(acc2 - mx) + __expf(acc3 - mx);
        se = warp_sum(se);
        float lse = mx + logf(se);
        float4 v;
        v.x = acc0 - lse; v.y = acc1 - lse; v.z = acc2 - lse; v.w = acc3 - lse;
        *(float4*)op = v;
    }
}

// ---------------- launch -----------------------------------------------------
extern "C" void kernel_launch(void* const* d_in, const int* in_sizes, int n_in,
                              void* d_out, int out_size) {
    const int*   edge  = (const int*)d_in[0];     // [2, E]
    const float* feats = (const float*)d_in[1];   // [N, 128]
    const float* W1    = (const float*)d_in[2];
    const float* a1s   = (const float*)d_in[3];
    const float* a1d   = (const float*)d_in[4];
    const float* b1    = (const float*)d_in[5];
    const float* W2    = (const float*)d_in[6];
    const float* a2s   = (const float*)d_in[7];
    const float* a2d   = (const float*)d_in[8];
    const float* b2    = (const float*)d_in[9];
    float* out = (float*)d_out;

    const int E = in_sizes[0] / 2;
    const int N = in_sizes[1] / DFEAT;
    const int* src = edge;
    const int* dst = edge + E;

    float *bufA, *bufB, *es, *ed;
    void *degP, *totP;
    cudaGetSymbolAddress((void**)&bufA, g_bufA);
    cudaGetSymbolAddress((void**)&bufB, g_bufB);
    cudaGetSymbolAddress((void**)&es, g_es);
    cudaGetSymbolAddress((void**)&ed, g_ed);
    cudaGetSymbolAddress(&degP, g_deg);
    cudaGetSymbolAddress(&totP, g_total);

    cudaFuncSetAttribute(gemm_tf32_kernel,
                         cudaFuncAttributeMaxDynamicSharedMemorySize, GEMM_SMEM);

    // CSR build (unordered node ranges; no scan needed)
    cudaMemsetAsync(degP, 0, N * sizeof(int));
    cudaMemsetAsync(totP, 0, sizeof(int));
    count_kernel<<<(E + 255) / 256, 256>>>(dst, E);
    offsets_kernel<<<(N + 255) / 256, 256>>>(N);
    scatter_kernel<<<(E + 255) / 256, 256>>>(src, dst, E);

    const int gemmGrid = (N + 127) / 128;
    const int eGrid    = (N * 32 + 255) / 256;
    const int aggGrid  = (N + 7) / 8;

    // Layer 1
    gemm_tf32_kernel<<<gemmGrid, 256, GEMM_SMEM>>>(feats, W1, bufA, N);
    compute_e_kernel<<<eGrid, 256>>>(bufA, a1s, a1d, es, ed, N);
    aggregate_kernel<<<aggGrid, 256>>>(es, ed, b1, bufB, N, 0);

    // Layer 2
    gemm_tf32_kernel<<<gemmGrid, 256, GEMM_SMEM>>>(bufB, W2, bufA, N);
    compute_e_kernel<<<eGrid, 256>>>(bufA, a2s, a2d, es, ed, N);
    aggregate_kernel<<<aggGrid, 256>>>(es, ed, b2, out, N, 1);
}

// round 6
// speedup vs baseline: 1.2465x; 1.2465x over previous
#include <cuda_runtime.h>
#include <cuda_bf16.h>
#include <cuda_fp16.h>
#include <cstdint>
#include <math.h>

// Problem constants (fixed by the reference)
#define NNODES 100000
#define NEDGES 1600000
#define DFEAT  128
#define HEADS  4
#define DHEAD  32
#define NEG_SLOPE 0.2f

// ---------------- scratch (static device globals; no allocations) ------------
__device__ int    g_deg[NNODES];
__device__ int    g_cursor[NNODES];
__device__ int    g_off[NNODES];
__device__ int    g_total;
__device__ int    g_csr[NEDGES];
__device__ float  g_w[(size_t)NEDGES * HEADS];      // spill path for deg>32 nodes
__device__ float  g_bufA[(size_t)NNODES * DFEAT];   // GEMM output h (fp32)
__device__ float  g_bufB[(size_t)NNODES * DFEAT];   // layer-1 aggregated + relu
__device__ float  g_es[NNODES * HEADS];
__device__ float  g_ed[NNODES * HEADS];

// ---------------- CSR build --------------------------------------------------
__global__ void count_kernel(const int* __restrict__ dst, int e) {
    int i = blockIdx.x * blockDim.x + threadIdx.x;
    if (i < e) atomicAdd(&g_deg[dst[i]], 1);
}

// Unordered CSR offsets: warp inclusive scan + one atomicAdd per warp.
__global__ void offsets_kernel(int n) {
    int i = blockIdx.x * blockDim.x + threadIdx.x;
    int lane = threadIdx.x & 31;
    int d = (i < n) ? g_deg[i] : 0;
    int inc = d;
#pragma unroll
    for (int o = 1; o < 32; o <<= 1) {
        int t = __shfl_up_sync(0xffffffffu, inc, o);
        if (lane >= o) inc += t;
    }
    int warpTot = __shfl_sync(0xffffffffu, inc, 31);
    int base = 0;
    if (lane == 31) base = atomicAdd(&g_total, warpTot);
    base = __shfl_sync(0xffffffffu, base, 31);
    int off = base + inc - d;
    if (i < n) { g_off[i] = off; g_cursor[i] = off; }
}

__global__ void scatter_kernel(const int* __restrict__ src,
                               const int* __restrict__ dst, int e) {
    int i = blockIdx.x * blockDim.x + threadIdx.x;
    if (i < e) {
        int d = dst[i];
        int slot = atomicAdd(&g_cursor[d], 1);
        g_csr[slot] = src[i];
    }
}

// ---------------- fused GEMM + attention-logit epilogue ----------------------
// out[M,128] = X[M,128] @ W[128,128] via tensor cores.
// 2-term TF32: W pre-split into (hi, lo) tf32 at staging; A rounded to tf32 hi.
//   D = a_hi*b_hi + a_hi*b_lo  (drops a_lo*b ~ 2^-11 relative)
// Epilogue computes es[row][h] = <h_row, asrc_h>, ed likewise, fully in-block.
#define XS_STRIDE 132
#define WS_STRIDE 136
#define GEMM_SMEM ((128 * XS_STRIDE + 2 * 128 * WS_STRIDE) * 4)

__device__ __forceinline__ uint32_t to_tf32(float x) {
    uint32_t r;
    asm("cvt.rna.tf32.f32 %0, %1;" : "=r"(r) : "f"(x));
    return r;
}

__device__ __forceinline__ void mma_tf32(float* d, const uint32_t* a, const uint32_t* b) {
    asm volatile(
        "mma.sync.aligned.m16n8k8.row.col.f32.tf32.tf32.f32 "
        "{%0,%1,%2,%3}, {%4,%5,%6,%7}, {%8,%9}, {%0,%1,%2,%3};\n"
        : "+f"(d[0]), "+f"(d[1]), "+f"(d[2]), "+f"(d[3])
        : "r"(a[0]), "r"(a[1]), "r"(a[2]), "r"(a[3]),
          "r"(b[0]), "r"(b[1]));
}

__global__ __launch_bounds__(256, 1)
void gemm_fused_kernel(const float* __restrict__ X, const float* __restrict__ W,
                       const float* __restrict__ asrc, const float* __restrict__ adst,
                       float* __restrict__ out, float* __restrict__ es,
                       float* __restrict__ ed, int M) {
    extern __shared__ float sm[];
    float* Xs  = sm;                               // [128][XS_STRIDE]
    uint32_t* Whi = (uint32_t*)(sm + 128 * XS_STRIDE);        // [128][WS_STRIDE]
    uint32_t* Wlo = Whi + 128 * WS_STRIDE;                    // [128][WS_STRIDE]
    int tid = threadIdx.x;
    int rowBase = blockIdx.x * 128;

    // Stage X tile (zero-pad OOB rows)
#pragma unroll 4
    for (int i = tid; i < 128 * 32; i += 256) {
        int r = i >> 5, c4 = (i & 31) << 2;
        int gr = rowBase + r;
        float4 v = make_float4(0.f, 0.f, 0.f, 0.f);
        if (gr < M) v = *(const float4*)&X[(size_t)gr * 128 + c4];
        *(float4*)&Xs[r * XS_STRIDE + c4] = v;
    }
    // Stage W pre-split into tf32 hi/lo
#pragma unroll 4
    for (int i = tid; i < 128 * 32; i += 256) {
        int r = i >> 5, c4 = (i & 31) << 2;
        float4 v = *(const float4*)&W[(size_t)r * 128 + c4];
        uint32_t h0 = to_tf32(v.x), h1 = to_tf32(v.y);
        uint32_t h2 = to_tf32(v.z), h3 = to_tf32(v.w);
        uint4 hv = make_uint4(h0, h1, h2, h3);
        *(uint4*)&Whi[r * WS_STRIDE + c4] = hv;
        uint4 lv;
        lv.x = to_tf32(v.x - __uint_as_float(h0));
        lv.y = to_tf32(v.y - __uint_as_float(h1));
        lv.z = to_tf32(v.z - __uint_as_float(h2));
        lv.w = to_tf32(v.w - __uint_as_float(h3));
        *(uint4*)&Wlo[r * WS_STRIDE + c4] = lv;
    }
    __syncthreads();

    int lane = tid & 31, warp = tid >> 5;
    int g = lane >> 2, t = lane & 3;
    int wm = (warp & 3) * 32;
    int wn = (warp >> 2) * 64;

    float acc[2][8][4];
#pragma unroll
    for (int mb = 0; mb < 2; mb++)
#pragma unroll
        for (int nb = 0; nb < 8; nb++)
#pragma unroll
            for (int i = 0; i < 4; i++) acc[mb][nb][i] = 0.f;

    for (int kc = 0; kc < 128; kc += 8) {
        uint32_t ahi[2][4];
#pragma unroll
        for (int mb = 0; mb < 2; mb++) {
            int r0 = wm + mb * 16;
            ahi[mb][0] = to_tf32(Xs[(r0 + g) * XS_STRIDE + kc + t]);
            ahi[mb][1] = to_tf32(Xs[(r0 + g + 8) * XS_STRIDE + kc + t]);
            ahi[mb][2] = to_tf32(Xs[(r0 + g) * XS_STRIDE + kc + t + 4]);
            ahi[mb][3] = to_tf32(Xs[(r0 + g + 8) * XS_STRIDE + kc + t + 4]);
        }
        uint32_t bhi[8][2], blo[8][2];
#pragma unroll
        for (int nb = 0; nb < 8; nb++) {
            int n = wn + nb * 8 + g;
            bhi[nb][0] = Whi[(kc + t) * WS_STRIDE + n];
            bhi[nb][1] = Whi[(kc + t + 4) * WS_STRIDE + n];
            blo[nb][0] = Wlo[(kc + t) * WS_STRIDE + n];
            blo[nb][1] = Wlo[(kc + t + 4) * WS_STRIDE + n];
        }
#pragma unroll
        for (int mb = 0; mb < 2; mb++)
#pragma unroll
            for (int nb = 0; nb < 8; nb++) {
                mma_tf32(acc[mb][nb], ahi[mb], bhi[nb]);
                mma_tf32(acc[mb][nb], ahi[mb], blo[nb]);
            }
    }

    // Store h and accumulate per-thread attention-logit partials
    float ps[2][2][2], pd[2][2][2];   // [mb][rowhalf][head-local]
#pragma unroll
    for (int a = 0; a < 2; a++)
#pragma unroll
        for (int b = 0; b < 2; b++)
#pragma unroll
            for (int c = 0; c < 2; c++) { ps[a][b][c] = 0.f; pd[a][b][c] = 0.f; }

#pragma unroll
    for (int mb = 0; mb < 2; mb++)
#pragma unroll
        for (int nb = 0; nb < 8; nb++) {
            int col = wn + nb * 8 + 2 * t;
            int hl = nb >> 2;
            float as0 = __ldg(&asrc[col]), as1 = __ldg(&asrc[col + 1]);
            float ad0 = __ldg(&adst[col]), ad1 = __ldg(&adst[col + 1]);
            float c0 = acc[mb][nb][0], c1 = acc[mb][nb][1];
            float c2 = acc[mb][nb][2], c3 = acc[mb][nb][3];
            ps[mb][0][hl] += c0 * as0 + c1 * as1;
            ps[mb][1][hl] += c2 * as0 + c3 * as1;
            pd[mb][0][hl] += c0 * ad0 + c1 * ad1;
            pd[mb][1][hl] += c2 * ad0 + c3 * ad1;

            int row0 = rowBase + wm + mb * 16 + g;
            if (row0 < M) {
                float2 v; v.x = c0; v.y = c1;
                *(float2*)&out[(size_t)row0 * 128 + col] = v;
            }
            int row1 = row0 + 8;
            if (row1 < M) {
                float2 v; v.x = c2; v.y = c3;
                *(float2*)&out[(size_t)row1 * 128 + col] = v;
            }
        }

    __syncthreads();                 // done reading Xs — reuse as esd
    float* esd = sm;                 // [128 rows][4 heads][2 (src,dst)]
#pragma unroll
    for (int mb = 0; mb < 2; mb++)
#pragma unroll
        for (int half = 0; half < 2; half++)
#pragma unroll
            for (int hl = 0; hl < 2; hl++) {
                float vs = ps[mb][half][hl];
                float vd = pd[mb][half][hl];
                vs += __shfl_xor_sync(0xffffffffu, vs, 1);
                vs += __shfl_xor_sync(0xffffffffu, vs, 2);
                vd += __shfl_xor_sync(0xffffffffu, vd, 1);
                vd += __shfl_xor_sync(0xffffffffu, vd, 2);
                if (t == 0) {
                    int row = wm + mb * 16 + half * 8 + g;
                    int head = (wn >> 5) + hl;
                    esd[row * 8 + head * 2 + 0] = vs;
                    esd[row * 8 + head * 2 + 1] = vd;
                }
            }
    __syncthreads();
    if (tid < 128) {
        int grow = rowBase + tid;
        if (grow < M) {
            float4 vs, vd;
            vs.x = esd[tid * 8 + 0]; vd.x = esd[tid * 8 + 1];
            vs.y = esd[tid * 8 + 2]; vd.y = esd[tid * 8 + 3];
            vs.z = esd[tid * 8 + 4]; vd.z = esd[tid * 8 + 5];
            vs.w = esd[tid * 8 + 6]; vd.w = esd[tid * 8 + 7];
            *(float4*)&es[grow * 4] = vs;
            *(float4*)&ed[grow * 4] = vd;
        }
    }
}

// ---------------- aggregation: one warp per destination node -----------------
__device__ __forceinline__ float warp_sum(float v) {
#pragma unroll
    for (int o = 16; o; o >>= 1) v += __shfl_xor_sync(0xffffffffu, v, o);
    return v;
}

__device__ __forceinline__ float warp_max(float v) {
#pragma unroll
    for (int o = 16; o; o >>= 1) v = fmaxf(v, __shfl_xor_sync(0xffffffffu, v, o));
    return v;
}

__device__ __forceinline__ float lrelu(float x) {
    return x > 0.f ? x : NEG_SLOPE * x;
}

// Layout: lane owns features [4*lane, 4*lane+4) -> all in head (lane>>3).
// mode 0: out = relu(agg + bias); mode 1: out = log_softmax(agg + bias)
__global__ __launch_bounds__(256)
void aggregate_kernel(const float* __restrict__ h, const float* __restrict__ es,
                      const float* __restrict__ ed, const float* __restrict__ bias,
                      float* __restrict__ out, int n, int mode) {
    __shared__ int   sm_s[8][32];
    __shared__ float sm_a[8][32][4];
    int wi = threadIdx.x >> 5;
    int w = blockIdx.x * 8 + wi;
    int lane = threadIdx.x & 31;
    if (w >= n) return;
    int beg = g_off[w];
    int deg = g_deg[w];
    int end = beg + deg;
    float4 edv = *(const float4*)&ed[w * 4];
    int head = lane >> 3;

    float acc0 = 0.f, acc1 = 0.f, acc2 = 0.f, acc3 = 0.f;

    if (deg <= 32) {
        int j = beg + lane;
        int s = 0;
        float c0 = -1e30f, c1 = -1e30f, c2 = -1e30f, c3 = -1e30f;
        if (j < end) {
            s = g_csr[j];
            float4 e = *(const float4*)&es[s * 4];
            c0 = lrelu(e.x + edv.x); c1 = lrelu(e.y + edv.y);
            c2 = lrelu(e.z + edv.z); c3 = lrelu(e.w + edv.w);
        }
        float m0 = warp_max(c0), m1 = warp_max(c1);
        float m2 = warp_max(c2), m3 = warp_max(c3);
        float w0 = 0.f, w1 = 0.f, w2 = 0.f, w3 = 0.f;
        if (j < end) {
            w0 = __expf(c0 - m0); w1 = __expf(c1 - m1);
            w2 = __expf(c2 - m2); w3 = __expf(c3 - m3);
        }
        float z0 = warp_sum(w0), z1 = warp_sum(w1);
        float z2 = warp_sum(w2), z3 = warp_sum(w3);
        float i0 = (z0 > 0.f) ? 1.f / z0 : 0.f;
        float i1 = (z1 > 0.f) ? 1.f / z1 : 0.f;
        float i2 = (z2 > 0.f) ? 1.f / z2 : 0.f;
        float i3 = (z3 > 0.f) ? 1.f / z3 : 0.f;

        sm_s[wi][lane] = s;
        *(float4*)&sm_a[wi][lane][0] = make_float4(w0 * i0, w1 * i1, w2 * i2, w3 * i3);
        __syncwarp();
#pragma unroll 4
        for (int k = 0; k < deg; k++) {
            int   sk = sm_s[wi][k];
            float b  = sm_a[wi][k][head];
            float4 hv = *(const float4*)&h[(size_t)sk * 128 + lane * 4];
            acc0 = fmaf(b, hv.x, acc0); acc1 = fmaf(b, hv.y, acc1);
            acc2 = fmaf(b, hv.z, acc2); acc3 = fmaf(b, hv.w, acc3);
        }
    } else {
        float m0 = -1e30f, m1 = -1e30f, m2 = -1e30f, m3 = -1e30f;
        for (int j = beg + lane; j < end; j += 32) {
            int s = g_csr[j];
            float4 e = *(const float4*)&es[s * 4];
            m0 = fmaxf(m0, lrelu(e.x + edv.x)); m1 = fmaxf(m1, lrelu(e.y + edv.y));
            m2 = fmaxf(m2, lrelu(e.z + edv.z)); m3 = fmaxf(m3, lrelu(e.w + edv.w));
        }
        m0 = warp_max(m0); m1 = warp_max(m1); m2 = warp_max(m2); m3 = warp_max(m3);
        float z0 = 0.f, z1 = 0.f, z2 = 0.f, z3 = 0.f;
        for (int j = beg + lane; j < end; j += 32) {
            int s = g_csr[j];
            float4 e = *(const float4*)&es[s * 4];
            float w0 = __expf(lrelu(e.x + edv.x) - m0);
            float w1 = __expf(lrelu(e.y + edv.y) - m1);
            float w2 = __expf(lrelu(e.z + edv.z) - m2);
            float w3 = __expf(lrelu(e.w + edv.w) - m3);
            *(float4*)&g_w[(size_t)j * 4] = make_float4(w0, w1, w2, w3);
            z0 += w0; z1 += w1; z2 += w2; z3 += w3;
        }
        z0 = warp_sum(z0); z1 = warp_sum(z1); z2 = warp_sum(z2); z3 = warp_sum(z3);
        float i0 = (z0 > 0.f) ? 1.f / z0 : 0.f;
        float i1 = (z1 > 0.f) ? 1.f / z1 : 0.f;
        float i2 = (z2 > 0.f) ? 1.f / z2 : 0.f;
        float i3 = (z3 > 0.f) ? 1.f / z3 : 0.f;

        for (int j0 = beg; j0 < end; j0 += 32) {
            int j = j0 + lane;
            __syncwarp();
            if (j < end) {
                sm_s[wi][lane] = g_csr[j];
                float4 wv = *(const float4*)&g_w[(size_t)j * 4];
                *(float4*)&sm_a[wi][lane][0] =
                    make_float4(wv.x * i0, wv.y * i1, wv.z * i2, wv.w * i3);
            }
            __syncwarp();
            int cnt = min(32, end - j0);
#pragma unroll 4
            for (int k = 0; k < cnt; k++) {
                int   sk = sm_s[wi][k];
                float b  = sm_a[wi][k][head];
                float4 hv = *(const float4*)&h[(size_t)sk * 128 + lane * 4];
                acc0 = fmaf(b, hv.x, acc0); acc1 = fmaf(b, hv.y, acc1);
                acc2 = fmaf(b, hv.z, acc2); acc3 = fmaf(b, hv.w, acc3);
            }
        }
    }

    float4 bv = *(const float4*)&bias[lane * 4];
    acc0 += bv.x; acc1 += bv.y; acc2 += bv.z; acc3 += bv.w;

    float* op = out + (size_t)w * 128 + lane * 4;
    if (mode == 0) {
        float4 v;
        v.x = fmaxf(acc0, 0.f); v.y = fmaxf(acc1, 0.f);
        v.z = fmaxf(acc2, 0.f); v.w = fmaxf(acc3, 0.f);
        *(float4*)op = v;
    } else {
        float mx = fmaxf(fmaxf(acc0, acc1), fmaxf(acc2, acc3));
        mx = warp_max(mx);
        float se = __expf(acc0 - mx) + __expf(acc1 - mx) +
                   __expf(acc2 - mx) + __expf(acc3 - mx);
        se = warp_sum(se);
        float lse = mx + logf(se);
        float4 v;
        v.x = acc0 - lse; v.y = acc1 - lse; v.z = acc2 - lse; v.w = acc3 - lse;
        *(float4*)op = v;
    }
}

// ---------------- launch -----------------------------------------------------
extern "C" void kernel_launch(void* const* d_in, const int* in_sizes, int n_in,
                              void* d_out, int out_size) {
    const int*   edge  = (const int*)d_in[0];     // [2, E]
    const float* feats = (const float*)d_in[1];   // [N, 128]
    const float* W1    = (const float*)d_in[2];
    const float* a1s   = (const float*)d_in[3];
    const float* a1d   = (const float*)d_in[4];
    const float* b1    = (const float*)d_in[5];
    const float* W2    = (const float*)d_in[6];
    const float* a2s   = (const float*)d_in[7];
    const float* a2d   = (const float*)d_in[8];
    const float* b2    = (const float*)d_in[9];
    float* out = (float*)d_out;

    const int E = in_sizes[0] / 2;
    const int N = in_sizes[1] / DFEAT;
    const int* src = edge;
    const int* dst = edge + E;

    float *bufA, *bufB, *es, *ed;
    void *degP, *totP;
    cudaGetSymbolAddress((void**)&bufA, g_bufA);
    cudaGetSymbolAddress((void**)&bufB, g_bufB);
    cudaGetSymbolAddress((void**)&es, g_es);
    cudaGetSymbolAddress((void**)&ed, g_ed);
    cudaGetSymbolAddress(&degP, g_deg);
    cudaGetSymbolAddress(&totP, g_total);

    cudaFuncSetAttribute(gemm_fused_kernel,
                         cudaFuncAttributeMaxDynamicSharedMemorySize, GEMM_SMEM);

    // CSR build (unordered node ranges; no scan needed)
    cudaMemsetAsync(degP, 0, N * sizeof(int));
    cudaMemsetAsync(totP, 0, sizeof(int));
    count_kernel<<<(E + 255) / 256, 256>>>(dst, E);
    offsets_kernel<<<(N + 255) / 256, 256>>>(N);
    scatter_kernel<<<(E + 255) / 256, 256>>>(src, dst, E);

    const int gemmGrid = (N + 127) / 128;
    const int aggGrid  = (N + 7) / 8;

    // Layer 1
    gemm_fused_kernel<<<gemmGrid, 256, GEMM_SMEM>>>(feats, W1, a1s, a1d, bufA, es, ed, N);
    aggregate_kernel<<<aggGrid, 256>>>(bufA, es, ed, b1, bufB, N, 0);

    // Layer 2
    gemm_fused_kernel<<<gemmGrid, 256, GEMM_SMEM>>>(bufB, W2, a2s, a2d, bufA, es, ed, N);
    aggregate_kernel<<<aggGrid, 256>>>(bufA, es, ed, b2, out, N, 1);
}

// round 7
// speedup vs baseline: 1.4195x; 1.1389x over previous
#include <cuda_runtime.h>
#include <cuda_bf16.h>
#include <cuda_fp16.h>
#include <cstdint>
#include <math.h>

// Problem constants (fixed by the reference)
#define NNODES 100000
#define NEDGES 1600000
#define DFEAT  128
#define HEADS  4
#define DHEAD  32
#define NEG_SLOPE 0.2f

// ---------------- scratch (static device globals; no allocations) ------------
__device__ int    g_deg[NNODES];
__device__ int    g_cursor[NNODES];
__device__ int    g_off[NNODES];
__device__ int    g_total;
__device__ int    g_csr[NEDGES];
__device__ float  g_w[(size_t)NEDGES * HEADS];      // spill path for deg>32 nodes
__device__ float  g_bufA[(size_t)NNODES * DFEAT];   // GEMM output h (fp32)
__device__ float  g_bufB[(size_t)NNODES * DFEAT];   // layer-1 aggregated + relu
__device__ float  g_es[NNODES * HEADS];
__device__ float  g_ed[NNODES * HEADS];

// ---------------- CSR build --------------------------------------------------
__global__ void count_kernel(const int* __restrict__ dst, int e) {
    int i = blockIdx.x * blockDim.x + threadIdx.x;
    if (i < e) atomicAdd(&g_deg[dst[i]], 1);
}

// Unordered CSR offsets: warp inclusive scan + one atomicAdd per warp.
__global__ void offsets_kernel(int n) {
    int i = blockIdx.x * blockDim.x + threadIdx.x;
    int lane = threadIdx.x & 31;
    int d = (i < n) ? g_deg[i] : 0;
    int inc = d;
#pragma unroll
    for (int o = 1; o < 32; o <<= 1) {
        int t = __shfl_up_sync(0xffffffffu, inc, o);
        if (lane >= o) inc += t;
    }
    int warpTot = __shfl_sync(0xffffffffu, inc, 31);
    int base = 0;
    if (lane == 31) base = atomicAdd(&g_total, warpTot);
    base = __shfl_sync(0xffffffffu, base, 31);
    int off = base + inc - d;
    if (i < n) { g_off[i] = off; g_cursor[i] = off; }
}

__global__ void scatter_kernel(const int* __restrict__ src,
                               const int* __restrict__ dst, int e) {
    int i = blockIdx.x * blockDim.x + threadIdx.x;
    if (i < e) {
        int d = dst[i];
        int slot = atomicAdd(&g_cursor[d], 1);
        g_csr[slot] = src[i];
    }
}

// ---------------- fused GEMM + attention-logit epilogue ----------------------
// out[M,128] = X[M,128] @ W[128,128], single-pass TF32 tensor cores.
// X staged pre-converted to tf32; W staged tf32 (hi only).
// M-tile = 64 -> ~101 KB smem -> 2 CTAs/SM (16 warps/SM).
// Warp (8 total) owns 32x32: wm=(warp&1)*32, wn=(warp>>1)*32; N-range == one head.
#define XT_STRIDE 132
#define WS_STRIDE 136
#define GEMM_SMEM ((64 * XT_STRIDE + 128 * WS_STRIDE) * 4)

__device__ __forceinline__ uint32_t to_tf32(float x) {
    uint32_t r;
    asm("cvt.rna.tf32.f32 %0, %1;" : "=r"(r) : "f"(x));
    return r;
}

__device__ __forceinline__ void mma_tf32(float* d, const uint32_t* a, const uint32_t* b) {
    asm volatile(
        "mma.sync.aligned.m16n8k8.row.col.f32.tf32.tf32.f32 "
        "{%0,%1,%2,%3}, {%4,%5,%6,%7}, {%8,%9}, {%0,%1,%2,%3};\n"
        : "+f"(d[0]), "+f"(d[1]), "+f"(d[2]), "+f"(d[3])
        : "r"(a[0]), "r"(a[1]), "r"(a[2]), "r"(a[3]),
          "r"(b[0]), "r"(b[1]));
}

__global__ __launch_bounds__(256, 2)
void gemm_fused_kernel(const float* __restrict__ X, const float* __restrict__ W,
                       const float* __restrict__ asrc, const float* __restrict__ adst,
                       float* __restrict__ out, float* __restrict__ es,
                       float* __restrict__ ed, int M) {
    extern __shared__ float sm[];
    uint32_t* Xs  = (uint32_t*)sm;                      // [64][XT_STRIDE] tf32
    uint32_t* Whi = (uint32_t*)sm + 64 * XT_STRIDE;     // [128][WS_STRIDE] tf32
    int tid = threadIdx.x;
    int rowBase = blockIdx.x * 64;

    // Stage X tile pre-converted to tf32 (zero-pad OOB rows)
#pragma unroll 2
    for (int i = tid; i < 64 * 32; i += 256) {
        int r = i >> 5, c4 = (i & 31) << 2;
        int gr = rowBase + r;
        float4 v = make_float4(0.f, 0.f, 0.f, 0.f);
        if (gr < M) v = *(const float4*)&X[(size_t)gr * 128 + c4];
        uint4 u;
        u.x = to_tf32(v.x); u.y = to_tf32(v.y);
        u.z = to_tf32(v.z); u.w = to_tf32(v.w);
        *(uint4*)&Xs[r * XT_STRIDE + c4] = u;
    }
    // Stage W converted to tf32
#pragma unroll 4
    for (int i = tid; i < 128 * 32; i += 256) {
        int r = i >> 5, c4 = (i & 31) << 2;
        float4 v = *(const float4*)&W[(size_t)r * 128 + c4];
        uint4 u;
        u.x = to_tf32(v.x); u.y = to_tf32(v.y);
        u.z = to_tf32(v.z); u.w = to_tf32(v.w);
        *(uint4*)&Whi[r * WS_STRIDE + c4] = u;
    }
    __syncthreads();

    int lane = tid & 31, warp = tid >> 5;
    int g = lane >> 2, t = lane & 3;
    int wm = (warp & 1) * 32;
    int wn = (warp >> 1) * 32;
    int head = warp >> 1;

    float acc[2][4][4];
#pragma unroll
    for (int mb = 0; mb < 2; mb++)
#pragma unroll
        for (int nb = 0; nb < 4; nb++)
#pragma unroll
            for (int i = 0; i < 4; i++) acc[mb][nb][i] = 0.f;

#pragma unroll 4
    for (int kc = 0; kc < 128; kc += 8) {
        uint32_t a[2][4];
#pragma unroll
        for (int mb = 0; mb < 2; mb++) {
            int r0 = wm + mb * 16;
            a[mb][0] = Xs[(r0 + g) * XT_STRIDE + kc + t];
            a[mb][1] = Xs[(r0 + g + 8) * XT_STRIDE + kc + t];
            a[mb][2] = Xs[(r0 + g) * XT_STRIDE + kc + t + 4];
            a[mb][3] = Xs[(r0 + g + 8) * XT_STRIDE + kc + t + 4];
        }
        uint32_t b[4][2];
#pragma unroll
        for (int nb = 0; nb < 4; nb++) {
            int n = wn + nb * 8 + g;
            b[nb][0] = Whi[(kc + t) * WS_STRIDE + n];
            b[nb][1] = Whi[(kc + t + 4) * WS_STRIDE + n];
        }
#pragma unroll
        for (int mb = 0; mb < 2; mb++)
#pragma unroll
            for (int nb = 0; nb < 4; nb++)
                mma_tf32(acc[mb][nb], a[mb], b[nb]);
    }

    // Store h and accumulate per-thread attention-logit partials.
    float ps[2][2], pd[2][2];   // [mb][rowhalf]; this warp's cols = one head
#pragma unroll
    for (int a = 0; a < 2; a++)
#pragma unroll
        for (int b = 0; b < 2; b++) { ps[a][b] = 0.f; pd[a][b] = 0.f; }

#pragma unroll
    for (int mb = 0; mb < 2; mb++)
#pragma unroll
        for (int nb = 0; nb < 4; nb++) {
            int col = wn + nb * 8 + 2 * t;
            float as0 = __ldg(&asrc[col]), as1 = __ldg(&asrc[col + 1]);
            float ad0 = __ldg(&adst[col]), ad1 = __ldg(&adst[col + 1]);
            float c0 = acc[mb][nb][0], c1 = acc[mb][nb][1];
            float c2 = acc[mb][nb][2], c3 = acc[mb][nb][3];
            ps[mb][0] += c0 * as0 + c1 * as1;
            ps[mb][1] += c2 * as0 + c3 * as1;
            pd[mb][0] += c0 * ad0 + c1 * ad1;
            pd[mb][1] += c2 * ad0 + c3 * ad1;

            int row0 = rowBase + wm + mb * 16 + g;
            if (row0 < M) {
                float2 v; v.x = c0; v.y = c1;
                *(float2*)&out[(size_t)row0 * 128 + col] = v;
            }
            int row1 = row0 + 8;
            if (row1 < M) {
                float2 v; v.x = c2; v.y = c3;
                *(float2*)&out[(size_t)row1 * 128 + col] = v;
            }
        }

    __syncthreads();                 // done reading Xs — reuse as esd stage
    float* esd = sm;                 // [64 rows][4 heads][2 (src,dst)]
#pragma unroll
    for (int mb = 0; mb < 2; mb++)
#pragma unroll
        for (int half = 0; half < 2; half++) {
            float vs = ps[mb][half];
            float vd = pd[mb][half];
            vs += __shfl_xor_sync(0xffffffffu, vs, 1);
            vs += __shfl_xor_sync(0xffffffffu, vs, 2);
            vd += __shfl_xor_sync(0xffffffffu, vd, 1);
            vd += __shfl_xor_sync(0xffffffffu, vd, 2);
            if (t == 0) {
                int row = wm + mb * 16 + half * 8 + g;
                esd[row * 8 + head * 2 + 0] = vs;
                esd[row * 8 + head * 2 + 1] = vd;
            }
        }
    __syncthreads();
    if (tid < 64) {
        int grow = rowBase + tid;
        if (grow < M) {
            float4 vs, vd;
            vs.x = esd[tid * 8 + 0]; vd.x = esd[tid * 8 + 1];
            vs.y = esd[tid * 8 + 2]; vd.y = esd[tid * 8 + 3];
            vs.z = esd[tid * 8 + 4]; vd.z = esd[tid * 8 + 5];
            vs.w = esd[tid * 8 + 6]; vd.w = esd[tid * 8 + 7];
            *(float4*)&es[grow * 4] = vs;
            *(float4*)&ed[grow * 4] = vd;
        }
    }
}

// ---------------- aggregation: one warp per destination node -----------------
__device__ __forceinline__ float warp_sum(float v) {
#pragma unroll
    for (int o = 16; o; o >>= 1) v += __shfl_xor_sync(0xffffffffu, v, o);
    return v;
}

__device__ __forceinline__ float warp_max(float v) {
#pragma unroll
    for (int o = 16; o; o >>= 1) v = fmaxf(v, __shfl_xor_sync(0xffffffffu, v, o));
    return v;
}

__device__ __forceinline__ float lrelu(float x) {
    return x > 0.f ? x : NEG_SLOPE * x;
}

// Layout: lane owns features [4*lane, 4*lane+4) -> all in head (lane>>3).
// mode 0: out = relu(agg + bias); mode 1: out = log_softmax(agg + bias)
__global__ __launch_bounds__(256)
void aggregate_kernel(const float* __restrict__ h, const float* __restrict__ es,
                      const float* __restrict__ ed, const float* __restrict__ bias,
                      float* __restrict__ out, int n, int mode) {
    __shared__ int   sm_s[8][32];
    __shared__ float sm_a[8][32][4];
    int wi = threadIdx.x >> 5;
    int w = blockIdx.x * 8 + wi;
    int lane = threadIdx.x & 31;
    if (w >= n) return;
    int beg = g_off[w];
    int deg = g_deg[w];
    int end = beg + deg;
    float4 edv = *(const float4*)&ed[w * 4];
    int head = lane >> 3;

    float acc0 = 0.f, acc1 = 0.f, acc2 = 0.f, acc3 = 0.f;

    if (deg <= 32) {
        int j = beg + lane;
        int s = 0;
        float c0 = -1e30f, c1 = -1e30f, c2 = -1e30f, c3 = -1e30f;
        if (j < end) {
            s = g_csr[j];
            float4 e = *(const float4*)&es[s * 4];
            c0 = lrelu(e.x + edv.x); c1 = lrelu(e.y + edv.y);
            c2 = lrelu(e.z + edv.z); c3 = lrelu(e.w + edv.w);
        }
        float m0 = warp_max(c0), m1 = warp_max(c1);
        float m2 = warp_max(c2), m3 = warp_max(c3);
        float w0 = 0.f, w1 = 0.f, w2 = 0.f, w3 = 0.f;
        if (j < end) {
            w0 = __expf(c0 - m0); w1 = __expf(c1 - m1);
            w2 = __expf(c2 - m2); w3 = __expf(c3 - m3);
        }
        float z0 = warp_sum(w0), z1 = warp_sum(w1);
        float z2 = warp_sum(w2), z3 = warp_sum(w3);
        float i0 = (z0 > 0.f) ? 1.f / z0 : 0.f;
        float i1 = (z1 > 0.f) ? 1.f / z1 : 0.f;
        float i2 = (z2 > 0.f) ? 1.f / z2 : 0.f;
        float i3 = (z3 > 0.f) ? 1.f / z3 : 0.f;

        sm_s[wi][lane] = s;
        *(float4*)&sm_a[wi][lane][0] = make_float4(w0 * i0, w1 * i1, w2 * i2, w3 * i3);
        __syncwarp();
#pragma unroll 4
        for (int k = 0; k < deg; k++) {
            int   sk = sm_s[wi][k];
            float b  = sm_a[wi][k][head];
            float4 hv = *(const float4*)&h[(size_t)sk * 128 + lane * 4];
            acc0 = fmaf(b, hv.x, acc0); acc1 = fmaf(b, hv.y, acc1);
            acc2 = fmaf(b, hv.z, acc2); acc3 = fmaf(b, hv.w, acc3);
        }
    } else {
        float m0 = -1e30f, m1 = -1e30f, m2 = -1e30f, m3 = -1e30f;
        for (int j = beg + lane; j < end; j += 32) {
            int s = g_csr[j];
            float4 e = *(const float4*)&es[s * 4];
            m0 = fmaxf(m0, lrelu(e.x + edv.x)); m1 = fmaxf(m1, lrelu(e.y + edv.y));
            m2 = fmaxf(m2, lrelu(e.z + edv.z)); m3 = fmaxf(m3, lrelu(e.w + edv.w));
        }
        m0 = warp_max(m0); m1 = warp_max(m1); m2 = warp_max(m2); m3 = warp_max(m3);
        float z0 = 0.f, z1 = 0.f, z2 = 0.f, z3 = 0.f;
        for (int j = beg + lane; j < end; j += 32) {
            int s = g_csr[j];
            float4 e = *(const float4*)&es[s * 4];
            float w0 = __expf(lrelu(e.x + edv.x) - m0);
            float w1 = __expf(lrelu(e.y + edv.y) - m1);
            float w2 = __expf(lrelu(e.z + edv.z) - m2);
            float w3 = __expf(lrelu(e.w + edv.w) - m3);
            *(float4*)&g_w[(size_t)j * 4] = make_float4(w0, w1, w2, w3);
            z0 += w0; z1 += w1; z2 += w2; z3 += w3;
        }
        z0 = warp_sum(z0); z1 = warp_sum(z1); z2 = warp_sum(z2); z3 = warp_sum(z3);
        float i0 = (z0 > 0.f) ? 1.f / z0 : 0.f;
        float i1 = (z1 > 0.f) ? 1.f / z1 : 0.f;
        float i2 = (z2 > 0.f) ? 1.f / z2 : 0.f;
        float i3 = (z3 > 0.f) ? 1.f / z3 : 0.f;

        for (int j0 = beg; j0 < end; j0 += 32) {
            int j = j0 + lane;
            __syncwarp();
            if (j < end) {
                sm_s[wi][lane] = g_csr[j];
                float4 wv = *(const float4*)&g_w[(size_t)j * 4];
                *(float4*)&sm_a[wi][lane][0] =
                    make_float4(wv.x * i0, wv.y * i1, wv.z * i2, wv.w * i3);
            }
            __syncwarp();
            int cnt = min(32, end - j0);
#pragma unroll 4
            for (int k = 0; k < cnt; k++) {
                int   sk = sm_s[wi][k];
                float b  = sm_a[wi][k][head];
                float4 hv = *(const float4*)&h[(size_t)sk * 128 + lane * 4];
                acc0 = fmaf(b, hv.x, acc0); acc1 = fmaf(b, hv.y, acc1);
                acc2 = fmaf(b, hv.z, acc2); acc3 = fmaf(b, hv.w, acc3);
            }
        }
    }

    float4 bv = *(const float4*)&bias[lane * 4];
    acc0 += bv.x; acc1 += bv.y; acc2 += bv.z; acc3 += bv.w;

    float* op = out + (size_t)w * 128 + lane * 4;
    if (mode == 0) {
        float4 v;
        v.x = fmaxf(acc0, 0.f); v.y = fmaxf(acc1, 0.f);
        v.z = fmaxf(acc2, 0.f); v.w = fmaxf(acc3, 0.f);
        *(float4*)op = v;
    } else {
        float mx = fmaxf(fmaxf(acc0, acc1), fmaxf(acc2, acc3));
        mx = warp_max(mx);
        float se = __expf(acc0 - mx) + __expf(acc1 - mx) +
                   __expf(acc2 - mx) + __expf(acc3 - mx);
        se = warp_sum(se);
        float lse = mx + logf(se);
        float4 v;
        v.x = acc0 - lse; v.y = acc1 - lse; v.z = acc2 - lse; v.w = acc3 - lse;
        *(float4*)op = v;
    }
}

// ---------------- launch -----------------------------------------------------
extern "C" void kernel_launch(void* const* d_in, const int* in_sizes, int n_in,
                              void* d_out, int out_size) {
    const int*   edge  = (const int*)d_in[0];     // [2, E]
    const float* feats = (const float*)d_in[1];   // [N, 128]
    const float* W1    = (const float*)d_in[2];
    const float* a1s   = (const float*)d_in[3];
    const float* a1d   = (const float*)d_in[4];
    const float* b1    = (const float*)d_in[5];
    const float* W2    = (const float*)d_in[6];
    const float* a2s   = (const float*)d_in[7];
    const float* a2d   = (const float*)d_in[8];
    const float* b2    = (const float*)d_in[9];
    float* out = (float*)d_out;

    const int E = in_sizes[0] / 2;
    const int N = in_sizes[1] / DFEAT;
    const int* src = edge;
    const int* dst = edge + E;

    float *bufA, *bufB, *es, *ed;
    void *degP, *totP;
    cudaGetSymbolAddress((void**)&bufA, g_bufA);
    cudaGetSymbolAddress((void**)&bufB, g_bufB);
    cudaGetSymbolAddress((void**)&es, g_es);
    cudaGetSymbolAddress((void**)&ed, g_ed);
    cudaGetSymbolAddress(&degP, g_deg);
    cudaGetSymbolAddress(&totP, g_total);

    cudaFuncSetAttribute(gemm_fused_kernel,
                         cudaFuncAttributeMaxDynamicSharedMemorySize, GEMM_SMEM);

    // CSR build (unordered node ranges; no scan needed)
    cudaMemsetAsync(degP, 0, N * sizeof(int));
    cudaMemsetAsync(totP, 0, sizeof(int));
    count_kernel<<<(E + 255) / 256, 256>>>(dst, E);
    offsets_kernel<<<(N + 255) / 256, 256>>>(N);
    scatter_kernel<<<(E + 255) / 256, 256>>>(src, dst, E);

    const int gemmGrid = (N + 63) / 64;
    const int aggGrid  = (N + 7) / 8;

    // Layer 1
    gemm_fused_kernel<<<gemmGrid, 256, GEMM_SMEM>>>(feats, W1, a1s, a1d, bufA, es, ed, N);
    aggregate_kernel<<<aggGrid, 256>>>(bufA, es, ed, b1, bufB, N, 0);

    // Layer 2
    gemm_fused_kernel<<<gemmGrid, 256, GEMM_SMEM>>>(bufB, W2, a2s, a2d, bufA, es, ed, N);
    aggregate_kernel<<<aggGrid, 256>>>(bufA, es, ed, b2, out, N, 1);
}